// round 14
// baseline (speedup 1.0000x reference)
#include <cuda_runtime.h>
#include <cstdint>

// GRU over T2=256; 4096 independent rows.
// Kernel 1 (precompute, 512 thr / 16 warps): pre[t][o][row] = x_t @ Wx + bias
//   for t in 1..255, two warp-groups each own half the t-range.
// Kernel 2 (sequential, unchanged from R13): 255-step recurrence, K=64,
//   acc initialized from prefetched pre[]. fp32 via packed fma.rn.f32x2.

#define T2V 256
#define DV  64
#define NCTA 128
#define NT  256
#define NTP 512
#define GSL 32
#define NPRE_T 255
#define PRE_STEP 6144            // 192 cols * 32 rows per (cta, t)

// 255 * 4096 * 192 floats = 802 MB scratch (sanctioned __device__ global)
__device__ float g_pre[(size_t)NPRE_T * 4096 * 192];

typedef unsigned long long ull;

__device__ __forceinline__ ull pk2(float lo, float hi) {
    ull r;
    asm("mov.b64 %0, {%1, %2};" : "=l"(r) : "f"(lo), "f"(hi));
    return r;
}
__device__ __forceinline__ float2 upk2(ull v) {
    float2 f;
    asm("mov.b64 {%0, %1}, %2;" : "=f"(f.x), "=f"(f.y) : "l"(v));
    return f;
}
__device__ __forceinline__ void ffma2(ull& d, ull a, ull b) {
    asm("fma.rn.f32x2 %0, %1, %2, %0;" : "+l"(d) : "l"(a), "l"(b));
}
__device__ __forceinline__ ull dl(double d) { return __double_as_longlong(d); }

__device__ __forceinline__ float fsig(float x) {
    float e;
    asm("ex2.approx.f32 %0, %1;" : "=f"(e) : "f"(x * -1.4426950408889634f));
    float r;
    asm("rcp.approx.f32 %0, %1;" : "=f"(r) : "f"(1.0f + e));
    return r;
}
__device__ __forceinline__ float ftanh_(float x) {
    return fmaf(2.0f, fsig(2.0f * x), -1.0f);
}

// ===========================================================================
// Kernel 1: precompute x-half pre-acts. o<64 -> r, 64..127 -> z, 128..191 -> h.
// pre[cta][t-1][o][row32], biases folded in. 512 threads: warp-group 0 covers
// t 1..128, group 1 covers t 129..255; 2 t's per pass, 64 passes.
// ===========================================================================
#define SXS 68                          // slab k-stride (272B: 16B-aligned)
#define PX_WX 0                         // 64*192
#define PX_SX (64*192)                  // 2 groups * 64*SXS
#define PX_FLOATS (PX_SX + 2*64*SXS)
#define PX_BYTES (PX_FLOATS * 4)

__global__ void __launch_bounds__(NTP, 1)
gru4d_pre_kernel(const float* __restrict__ x,
                 const float* __restrict__ kh,
                 const float* __restrict__ kr,
                 const float* __restrict__ kz,
                 const float* __restrict__ bh,
                 const float* __restrict__ br,
                 const float* __restrict__ bz) {
    extern __shared__ float sm[];
    float* sWx = sm + PX_WX;

    const int tid  = threadIdx.x;
    const int grp  = tid >> 8;            // warp-group 0/1 (t-range halves)
    const int gtid = tid & 255;
    const int w8   = gtid >> 5;           // warp within group 0..7
    const int lane = tid & 31;
    const int rg4  = (lane >> 2) * 4;     // rows rg4..rg4+3
    const int cg   = lane & 3;
    const int ob   = 24 * w8 + 6 * cg;    // 6 output cols ob..ob+5 (of 192)
    const int row0 = blockIdx.x * 32;
    const size_t rstr = (size_t)T2V * DV;
    const size_t base = (size_t)blockIdx.x * NPRE_T * PRE_STEP;

    float* sx = sm + PX_SX + grp * (64 * SXS);

    // stage weights (x-half rows k=0..63 of each gate kernel), all 512 threads
    for (int idx = tid; idx < 64 * 192; idx += NTP) {
        int k = idx / 192, o = idx % 192;
        float v;
        if (o < 64)       v = kr[k * 64 + o];
        else if (o < 128) v = kz[k * 64 + (o - 64)];
        else              v = kh[k * 64 + (o - 128)];
        sWx[idx] = v;
    }
    // biases for this thread's 6 cols
    float bb[6];
    #pragma unroll
    for (int j = 0; j < 6; j++) {
        int o = ob + j;
        bb[j] = (o < 64) ? br[o] : (o < 128) ? bz[o - 64] : bh[o - 128];
    }

    for (int p = 0; p < 64; ++p) {
        const int t0 = 1 + 2 * p + grp * 128;
        __syncthreads();   // previous pass done reading sx
        // stage x^T for t0, t0+1 : 2*32*64 = 4096 floats per group
        #pragma unroll
        for (int i = 0; i < 4; i++) {
            int u = gtid + 256 * i;          // 0..1023
            int kq = u & 15;
            int r  = (u >> 4) & 31;
            int tt = u >> 9;                 // 0/1
            int t = t0 + tt;
            if (t < T2V) {
                float4 v = *(const float4*)&x[(size_t)(row0 + r) * rstr
                                              + (size_t)t * DV + 4 * kq];
                sx[(4 * kq + 0) * SXS + tt * 32 + r] = v.x;
                sx[(4 * kq + 1) * SXS + tt * 32 + r] = v.y;
                sx[(4 * kq + 2) * SXS + tt * 32 + r] = v.z;
                sx[(4 * kq + 3) * SXS + tt * 32 + r] = v.w;
            }
        }
        __syncthreads();

        // acc[rowpair][tt][col]
        ull acc[2][2][6];
        #pragma unroll
        for (int tt = 0; tt < 2; tt++)
            #pragma unroll
            for (int j = 0; j < 6; j++) {
                acc[0][tt][j] = pk2(bb[j], bb[j]);
                acc[1][tt][j] = pk2(bb[j], bb[j]);
            }

        #pragma unroll 4
        for (int k = 0; k < 64; ++k) {
            ull wb[6];
            #pragma unroll
            for (int jj = 0; jj < 3; jj++) {
                float2 wv = *(const float2*)&sWx[k * 192 + ob + 2 * jj];
                wb[2 * jj]     = pk2(wv.x, wv.x);
                wb[2 * jj + 1] = pk2(wv.y, wv.y);
            }
            #pragma unroll
            for (int tt = 0; tt < 2; tt++) {
                double2 gd = *(const double2*)&sx[k * SXS + tt * 32 + rg4];
                ull ga = dl(gd.x), gb = dl(gd.y);
                #pragma unroll
                for (int j = 0; j < 6; j++) {
                    ffma2(acc[0][tt][j], ga, wb[j]);
                    ffma2(acc[1][tt][j], gb, wb[j]);
                }
            }
        }

        // store
        #pragma unroll
        for (int tt = 0; tt < 2; tt++) {
            int t = t0 + tt;
            if (t < T2V) {
                float* pp = g_pre + base + (size_t)(t - 1) * PRE_STEP;
                #pragma unroll
                for (int j = 0; j < 6; j++) {
                    float2 lo = upk2(acc[0][tt][j]);
                    float2 hi = upk2(acc[1][tt][j]);
                    *(float4*)&pp[(ob + j) * 32 + rg4] =
                        make_float4(lo.x, lo.y, hi.x, hi.y);
                }
            }
        }
    }
}

// ===========================================================================
// Kernel 2: sequential recurrence, K=64 (h-part only). Unchanged from R13.
// ===========================================================================
#define SQ_W1  0                         // 64*128 : rows 64..127 of (Wr|Wz)
#define SQ_WH2 (64*128)                  // 64*64  : rows 64..127 of Wh
#define SQ_HB  (SQ_W1 + 64*128 + 64*64)  // 64*GSL : h[c][row]
#define SQ_GHR (SQ_HB + 64*GSL)          // 64*GSL : (h*r)[c][row]
#define SQ_ZB  (SQ_GHR + 64*GSL)         // 64*GSL : z[c][row]
#define SQ_FLOATS (SQ_ZB + 64*GSL)
#define SQ_BYTES (SQ_FLOATS * 4)

__global__ void __launch_bounds__(NT, 1)
gru4d_seq_kernel(const float* __restrict__ x,
                 const float* __restrict__ kh,
                 const float* __restrict__ kr,
                 const float* __restrict__ kz,
                 float* __restrict__ out) {
    extern __shared__ float sm[];
    float* sW1  = sm + SQ_W1;
    float* sWh2 = sm + SQ_WH2;
    float* shb  = sm + SQ_HB;
    float* sghr = sm + SQ_GHR;
    float* szb  = sm + SQ_ZB;

    const int tid  = threadIdx.x;
    const int w    = tid >> 5;
    const int lane = tid & 31;
    const int rg4  = (lane >> 2) * 4;
    const int cg   = lane & 3;
    const int obase  = 16 * w + 4 * cg;   // phase-1 cols (of 128)
    const int c2base = 8 * w + 2 * cg;    // phase-2 cols (of 64)
    const int row0 = blockIdx.x * 32;
    const size_t rstr = (size_t)T2V * DV;
    const size_t base = (size_t)blockIdx.x * NPRE_T * PRE_STEP;

    // stage h-half weights (rows 64..127)
    for (int idx = tid; idx < 64 * 128; idx += NT) {
        int k = idx >> 7, o = idx & 127;
        sW1[idx] = (o < 64) ? kr[(64 + k) * 64 + o] : kz[(64 + k) * 64 + (o - 64)];
    }
    for (int idx = tid; idx < 64 * 64; idx += NT) {
        int k = idx >> 6, o = idx & 63;
        sWh2[idx] = kh[(64 + k) * 64 + o];
    }

    // init h0 = x[:,:,0,:]
    #pragma unroll
    for (int j = 0; j < 2; j++) {
        int c = c2base + j;
        #pragma unroll
        for (int i = 0; i < 4; i++)
            shb[c * GSL + rg4 + i] = x[(size_t)(row0 + rg4 + i) * rstr + c];
    }
    __syncthreads();

    // preload pre-acts for t=1
    float4 pv1[4], pv2[2];
    {
        const float* pp = g_pre + base;   // t=1
        #pragma unroll
        for (int j = 0; j < 4; j++)
            pv1[j] = *(const float4*)&pp[(obase + j) * 32 + rg4];
        #pragma unroll
        for (int j = 0; j < 2; j++)
            pv2[j] = *(const float4*)&pp[(128 + c2base + j) * 32 + rg4];
    }

    for (int t = 1; t < T2V; ++t) {
        // prefetch pre-acts for t+1 (hidden under phase-1)
        float4 pn1[4], pn2[2];
        if (t < T2V - 1) {
            const float* pp = g_pre + base + (size_t)t * PRE_STEP;  // t+1
            #pragma unroll
            for (int j = 0; j < 4; j++)
                pn1[j] = *(const float4*)&pp[(obase + j) * 32 + rg4];
            #pragma unroll
            for (int j = 0; j < 2; j++)
                pn2[j] = *(const float4*)&pp[(128 + c2base + j) * 32 + rg4];
        }

        // ===== phase 1: r|z += h @ W1  (K = 64) =====
        ull acc[4][2];
        #pragma unroll
        for (int j = 0; j < 4; j++) {
            acc[j][0] = pk2(pv1[j].x, pv1[j].y);
            acc[j][1] = pk2(pv1[j].z, pv1[j].w);
        }
        #pragma unroll 8
        for (int k = 0; k < 64; k++) {
            float4 wv = *(const float4*)&sW1[k * 128 + obase];
            double2 gd = *(const double2*)&shb[k * GSL + rg4];
            ull ga = dl(gd.x), gb = dl(gd.y);
            ull W0 = pk2(wv.x, wv.x), W1 = pk2(wv.y, wv.y);
            ull W2 = pk2(wv.z, wv.z), W3 = pk2(wv.w, wv.w);
            ffma2(acc[0][0], ga, W0); ffma2(acc[0][1], gb, W0);
            ffma2(acc[1][0], ga, W1); ffma2(acc[1][1], gb, W1);
            ffma2(acc[2][0], ga, W2); ffma2(acc[2][1], gb, W2);
            ffma2(acc[3][0], ga, W3); ffma2(acc[3][1], gb, W3);
        }

        // epilogue 1
        if (w < 4) {
            #pragma unroll
            for (int j = 0; j < 4; j++) {
                int c = obase + j;                  // r col
                float2 p0 = upk2(acc[j][0]);
                float2 p1 = upk2(acc[j][1]);
                float s0 = fsig(p0.x), s1 = fsig(p0.y);
                float s2 = fsig(p1.x), s3 = fsig(p1.y);
                float4 h4 = *(const float4*)&shb[c * GSL + rg4];
                *(float4*)&sghr[c * GSL + rg4] =
                    make_float4(h4.x * s0, h4.y * s1, h4.z * s2, h4.w * s3);
            }
        } else {
            #pragma unroll
            for (int j = 0; j < 4; j++) {
                int c = obase - 64 + j;             // z col
                float2 p0 = upk2(acc[j][0]);
                float2 p1 = upk2(acc[j][1]);
                *(float4*)&szb[c * GSL + rg4] =
                    make_float4(fsig(p0.x), fsig(p0.y), fsig(p1.x), fsig(p1.y));
            }
        }
        __syncthreads();   // (h*r, z) published; all phase-1 reads of shb done

        // ===== phase 2: hcand += (h*r) @ Wh2  (K = 64) =====
        ull a2[2][2];
        a2[0][0] = pk2(pv2[0].x, pv2[0].y); a2[0][1] = pk2(pv2[0].z, pv2[0].w);
        a2[1][0] = pk2(pv2[1].x, pv2[1].y); a2[1][1] = pk2(pv2[1].z, pv2[1].w);

        #pragma unroll 8
        for (int k = 0; k < 64; k++) {
            float2 wv = *(const float2*)&sWh2[k * 64 + c2base];
            double2 gd = *(const double2*)&sghr[k * GSL + rg4];
            ull ga = dl(gd.x), gb = dl(gd.y);
            ull W0 = pk2(wv.x, wv.x), W1 = pk2(wv.y, wv.y);
            ffma2(a2[0][0], ga, W0); ffma2(a2[0][1], gb, W0);
            ffma2(a2[1][0], ga, W1); ffma2(a2[1][1], gb, W1);
        }

        // epilogue 2: tanh + blend; publish h
        #pragma unroll
        for (int j = 0; j < 2; j++) {
            int c = c2base + j;
            float2 p0 = upk2(a2[j][0]);
            float2 p1 = upk2(a2[j][1]);
            float hc0 = ftanh_(p0.x), hc1 = ftanh_(p0.y);
            float hc2 = ftanh_(p1.x), hc3 = ftanh_(p1.y);
            float4 z4 = *(const float4*)&szb[c * GSL + rg4];
            float4 h4 = *(const float4*)&shb[c * GSL + rg4];
            *(float4*)&shb[c * GSL + rg4] =
                make_float4(fmaf(z4.x, hc0 - h4.x, h4.x),
                            fmaf(z4.y, hc1 - h4.y, h4.y),
                            fmaf(z4.z, hc2 - h4.z, h4.z),
                            fmaf(z4.w, hc3 - h4.w, h4.w));
        }
        pv1[0] = pn1[0]; pv1[1] = pn1[1]; pv1[2] = pn1[2]; pv1[3] = pn1[3];
        pv2[0] = pn2[0]; pv2[1] = pn2[1];
        __syncthreads();   // h published for next step
    }

    // write h_final
    #pragma unroll
    for (int j = 0; j < 2; j++) {
        int c = c2base + j;
        float4 h4 = *(const float4*)&shb[c * GSL + rg4];
        out[(size_t)(row0 + rg4 + 0) * DV + c] = h4.x;
        out[(size_t)(row0 + rg4 + 1) * DV + c] = h4.y;
        out[(size_t)(row0 + rg4 + 2) * DV + c] = h4.z;
        out[(size_t)(row0 + rg4 + 3) * DV + c] = h4.w;
    }
}

extern "C" void kernel_launch(void* const* d_in, const int* in_sizes, int n_in,
                              void* d_out, int out_size) {
    const float* x  = (const float*)d_in[0];
    const float* kh = (const float*)d_in[1];
    const float* kr = (const float*)d_in[2];
    const float* kz = (const float*)d_in[3];
    const float* bh = (const float*)d_in[4];
    const float* br = (const float*)d_in[5];
    const float* bz = (const float*)d_in[6];
    float* out = (float*)d_out;

    static bool attr_set = false;
    if (!attr_set) {
        cudaFuncSetAttribute(gru4d_pre_kernel,
                             cudaFuncAttributeMaxDynamicSharedMemorySize, PX_BYTES);
        cudaFuncSetAttribute(gru4d_seq_kernel,
                             cudaFuncAttributeMaxDynamicSharedMemorySize, SQ_BYTES);
        attr_set = true;
    }
    gru4d_pre_kernel<<<NCTA, NTP, PX_BYTES>>>(x, kh, kr, kz, bh, br, bz);
    gru4d_seq_kernel<<<NCTA, NT, SQ_BYTES>>>(x, kh, kr, kz, out);
}

// round 16
// speedup vs baseline: 1.0410x; 1.0410x over previous
#include <cuda_runtime.h>
#include <cuda_bf16.h>
#include <cstdint>

// GRU over T2=256; 4096 independent rows.
// Kernel 1 (pre, mma.sync bf16 hi/lo): pre[t][o][row] = x_t @ Wx + bias,
//   3 cross products (hh, hl, lh), fp32 accum -> ~1.5e-5 accuracy.
// Kernel 2 (seq, unchanged R13): 255-step recurrence, K=64 h-part only,
//   fp32 packed fma.rn.f32x2, acc initialized from prefetched pre[].

#define T2V 256
#define DV  64
#define NCTA 128
#define NT  256
#define GSL 32
#define NPRE_T 255
#define PRE_STEP 6144            // 192 cols * 32 rows per (row-block, t)

// 255 * 4096 * 192 floats = 802 MB scratch (sanctioned __device__ global)
__device__ float g_pre[(size_t)NPRE_T * 4096 * 192];

typedef unsigned long long ull;

// ---------------- packed f32x2 + activation helpers (seq kernel) -----------
__device__ __forceinline__ ull pk2(float lo, float hi) {
    ull r;
    asm("mov.b64 %0, {%1, %2};" : "=l"(r) : "f"(lo), "f"(hi));
    return r;
}
__device__ __forceinline__ float2 upk2(ull v) {
    float2 f;
    asm("mov.b64 {%0, %1}, %2;" : "=f"(f.x), "=f"(f.y) : "l"(v));
    return f;
}
__device__ __forceinline__ void ffma2(ull& d, ull a, ull b) {
    asm("fma.rn.f32x2 %0, %1, %2, %0;" : "+l"(d) : "l"(a), "l"(b));
}
__device__ __forceinline__ ull dl(double d) { return __double_as_longlong(d); }

__device__ __forceinline__ float fsig(float x) {
    float e;
    asm("ex2.approx.f32 %0, %1;" : "=f"(e) : "f"(x * -1.4426950408889634f));
    float r;
    asm("rcp.approx.f32 %0, %1;" : "=f"(r) : "f"(1.0f + e));
    return r;
}
__device__ __forceinline__ float ftanh_(float x) {
    return fmaf(2.0f, fsig(2.0f * x), -1.0f);
}

// ---------------- mma.sync helper (baseline PTX, no sm_103a features) ------
__device__ __forceinline__ void mma16816(float* c, uint32_t a0, uint32_t a1,
                                         uint32_t a2, uint32_t a3,
                                         uint32_t b0, uint32_t b1) {
    asm volatile("mma.sync.aligned.m16n8k16.row.col.f32.bf16.bf16.f32 "
                 "{%0,%1,%2,%3}, {%4,%5,%6,%7}, {%8,%9}, {%0,%1,%2,%3};"
                 : "+f"(c[0]), "+f"(c[1]), "+f"(c[2]), "+f"(c[3])
                 : "r"(a0), "r"(a1), "r"(a2), "r"(a3), "r"(b0), "r"(b1));
}

__device__ __forceinline__ uint32_t pbf2(float a, float b) {
    __nv_bfloat162 t = __floats2bfloat162_rn(a, b);
    uint32_t u;
    __builtin_memcpy(&u, &t, 4);
    return u;
}

// pre-kernel SMEM layout (uint32 units). Fragment rows stride 36 -> the
// fragment LDS pattern (lane -> row=lane/4, j=lane%4) maps bank = lane,
// conflict-free.
#define SA_HI 0                        // A hi: 128 m-rows x 32 kpairs (+pad)
#define SA_LO (SA_HI + 128 * 36)
#define SB_HI (SA_LO + 128 * 36)       // B hi: 192 o-rows x 32 kpairs (+pad)
#define SB_LO (SB_HI + 192 * 36)
#define SBIAS (SB_LO + 192 * 36)       // 192 floats
#define PRE_U32 (SBIAS + 192)
#define PRE_SMEM_BYTES (PRE_U32 * 4)

// ===========================================================================
// Kernel 1: mma.sync precompute. grid = (64 t-blocks, 128 row-blocks).
// M-tile = 4 t x 32 rows (m = tt*32 + r); o: gate g at [64g, 64g+64).
// ===========================================================================
__global__ void __launch_bounds__(256, 1)
gru4d_pre_mma(const float* __restrict__ x,
              const float* __restrict__ kh,
              const float* __restrict__ kr,
              const float* __restrict__ kz,
              const float* __restrict__ bh,
              const float* __restrict__ br,
              const float* __restrict__ bz) {
    extern __shared__ uint32_t su[];
    uint32_t* sAh = su + SA_HI;
    uint32_t* sAl = su + SA_LO;
    uint32_t* sBh = su + SB_HI;
    uint32_t* sBl = su + SB_LO;
    float*  sbias = (float*)(su + SBIAS);

    const int tid = threadIdx.x, w = tid >> 5, lane = tid & 31;
    const int l4 = lane >> 2, lm = lane & 3;
    const int tb = blockIdx.x, rb = blockIdx.y;
    const int t0 = 1 + 4 * tb;
    const int row0 = rb * 32;
    const size_t rstr = (size_t)T2V * DV;

    // ---- stage A: x[t0..t0+3][row0..+31] -> bf16 hi/lo k-pairs ----
    #pragma unroll
    for (int i = 0; i < 8; i++) {
        int u  = tid + 256 * i;          // 0..2047
        int kq = u & 15;                 // float4 index within D=64
        int m  = u >> 4;                 // tt*32 + r
        int r  = m & 31, tt = m >> 5;
        int t  = t0 + tt; if (t > 255) t = 255;   // clamp (tail rows unused)
        float4 v = *(const float4*)&x[(size_t)(row0 + r) * rstr
                                      + (size_t)t * DV + 4 * kq];
        float hx = __bfloat162float(__float2bfloat16(v.x));
        float hy = __bfloat162float(__float2bfloat16(v.y));
        float hz = __bfloat162float(__float2bfloat16(v.z));
        float hw = __bfloat162float(__float2bfloat16(v.w));
        uint32_t* ph = &sAh[m * 36 + 2 * kq];
        uint32_t* pl = &sAl[m * 36 + 2 * kq];
        ph[0] = pbf2(hx, hy);           ph[1] = pbf2(hz, hw);
        pl[0] = pbf2(v.x - hx, v.y - hy); pl[1] = pbf2(v.z - hz, v.w - hw);
    }

    // ---- stage B: W[k][o] -> [o][kpair] bf16 hi/lo (192 o-rows) ----
    for (int v = tid; v < 192 * 32; v += 256) {
        int o = v >> 5, j = v & 31;           // o 0..191, kpair 0..31
        int g = o >> 6, oc = o & 63;
        const float* W = (g == 0) ? kr : (g == 1) ? kz : kh;
        float w0 = W[(2 * j) * 64 + oc];
        float w1 = W[(2 * j + 1) * 64 + oc];
        float h0 = __bfloat162float(__float2bfloat16(w0));
        float h1 = __bfloat162float(__float2bfloat16(w1));
        sBh[o * 36 + j] = pbf2(h0, h1);
        sBl[o * 36 + j] = pbf2(w0 - h0, w1 - h1);
    }

    // ---- stage bias ----
    for (int o = tid; o < 192; o += 256)
        sbias[o] = (o < 64) ? br[o] : (o < 128) ? bz[o - 64] : bh[o - 128];

    __syncthreads();

    // ---- MMAs: warp w owns m-rows [16w, 16w+16); 24 n-tiles; 4 k-steps;
    //      3 combos (Ahi*Bhi, Ahi*Blo, Alo*Bhi) accumulated in fp32 ----
    float acc[24][4];
    #pragma unroll
    for (int nt = 0; nt < 24; nt++)
        #pragma unroll
        for (int e = 0; e < 4; e++) acc[nt][e] = 0.0f;

    const int r0 = w * 16 + l4;
    #pragma unroll
    for (int comb = 0; comb < 3; comb++) {
        const uint32_t* A = (comb == 2) ? sAl : sAh;
        const uint32_t* B = (comb == 1) ? sBl : sBh;
        #pragma unroll
        for (int ks = 0; ks < 4; ks++) {
            int j0 = ks * 8 + lm;
            uint32_t a0 = A[r0 * 36 + j0];
            uint32_t a1 = A[(r0 + 8) * 36 + j0];
            uint32_t a2 = A[r0 * 36 + j0 + 4];
            uint32_t a3 = A[(r0 + 8) * 36 + j0 + 4];
            #pragma unroll
            for (int nt = 0; nt < 24; nt++) {
                uint32_t b0 = B[(nt * 8 + l4) * 36 + j0];
                uint32_t b1 = B[(nt * 8 + l4) * 36 + j0 + 4];
                mma16816(acc[nt], a0, a1, a2, a3, b0, b1);
            }
        }
    }

    // ---- epilogue: add bias, store in [o][row32] layout ----
    {
        const int tt = w >> 1;                 // m = 16w + l4 -> tt = m>>5
        const int t = t0 + tt;
        if (t <= 255) {
            const int rl = (w & 1) * 16 + l4;  // row within 32-row t-slab
            float* pp = g_pre + (size_t)rb * NPRE_T * PRE_STEP
                              + (size_t)(t - 1) * PRE_STEP;
            #pragma unroll
            for (int nt = 0; nt < 24; nt++) {
                int n0 = nt * 8 + lm * 2;
                float b0v = sbias[n0], b1v = sbias[n0 + 1];
                pp[n0 * 32 + rl]            = acc[nt][0] + b0v;
                pp[(n0 + 1) * 32 + rl]      = acc[nt][1] + b1v;
                pp[n0 * 32 + rl + 8]        = acc[nt][2] + b0v;
                pp[(n0 + 1) * 32 + rl + 8]  = acc[nt][3] + b1v;
            }
        }
    }
}

// ===========================================================================
// Kernel 2: sequential recurrence, K=64 (h-part only). Unchanged from R13.
// ===========================================================================
#define SQ_W1  0                         // 64*128 : rows 64..127 of (Wr|Wz)
#define SQ_WH2 (64*128)                  // 64*64  : rows 64..127 of Wh
#define SQ_HB  (SQ_W1 + 64*128 + 64*64)  // 64*GSL : h[c][row]
#define SQ_GHR (SQ_HB + 64*GSL)          // 64*GSL : (h*r)[c][row]
#define SQ_ZB  (SQ_GHR + 64*GSL)         // 64*GSL : z[c][row]
#define SQ_FLOATS (SQ_ZB + 64*GSL)
#define SQ_BYTES (SQ_FLOATS * 4)

__global__ void __launch_bounds__(NT, 1)
gru4d_seq_kernel(const float* __restrict__ x,
                 const float* __restrict__ kh,
                 const float* __restrict__ kr,
                 const float* __restrict__ kz,
                 float* __restrict__ out) {
    extern __shared__ float sm[];
    float* sW1  = sm + SQ_W1;
    float* sWh2 = sm + SQ_WH2;
    float* shb  = sm + SQ_HB;
    float* sghr = sm + SQ_GHR;
    float* szb  = sm + SQ_ZB;

    const int tid  = threadIdx.x;
    const int w    = tid >> 5;
    const int lane = tid & 31;
    const int rg4  = (lane >> 2) * 4;
    const int cg   = lane & 3;
    const int obase  = 16 * w + 4 * cg;   // phase-1 cols (of 128)
    const int c2base = 8 * w + 2 * cg;    // phase-2 cols (of 64)
    const int row0 = blockIdx.x * 32;
    const size_t rstr = (size_t)T2V * DV;
    const size_t base = (size_t)blockIdx.x * NPRE_T * PRE_STEP;

    for (int idx = tid; idx < 64 * 128; idx += NT) {
        int k = idx >> 7, o = idx & 127;
        sW1[idx] = (o < 64) ? kr[(64 + k) * 64 + o] : kz[(64 + k) * 64 + (o - 64)];
    }
    for (int idx = tid; idx < 64 * 64; idx += NT) {
        int k = idx >> 6, o = idx & 63;
        sWh2[idx] = kh[(64 + k) * 64 + o];
    }

    #pragma unroll
    for (int j = 0; j < 2; j++) {
        int c = c2base + j;
        #pragma unroll
        for (int i = 0; i < 4; i++)
            shb[c * GSL + rg4 + i] = x[(size_t)(row0 + rg4 + i) * rstr + c];
    }
    __syncthreads();

    float4 pv1[4], pv2[2];
    {
        const float* pp = g_pre + base;   // t=1
        #pragma unroll
        for (int j = 0; j < 4; j++)
            pv1[j] = *(const float4*)&pp[(obase + j) * 32 + rg4];
        #pragma unroll
        for (int j = 0; j < 2; j++)
            pv2[j] = *(const float4*)&pp[(128 + c2base + j) * 32 + rg4];
    }

    for (int t = 1; t < T2V; ++t) {
        float4 pn1[4], pn2[2];
        if (t < T2V - 1) {
            const float* pp = g_pre + base + (size_t)t * PRE_STEP;  // t+1
            #pragma unroll
            for (int j = 0; j < 4; j++)
                pn1[j] = *(const float4*)&pp[(obase + j) * 32 + rg4];
            #pragma unroll
            for (int j = 0; j < 2; j++)
                pn2[j] = *(const float4*)&pp[(128 + c2base + j) * 32 + rg4];
        }

        // ===== phase 1: r|z += h @ W1  (K = 64) =====
        ull acc[4][2];
        #pragma unroll
        for (int j = 0; j < 4; j++) {
            acc[j][0] = pk2(pv1[j].x, pv1[j].y);
            acc[j][1] = pk2(pv1[j].z, pv1[j].w);
        }
        #pragma unroll 8
        for (int k = 0; k < 64; k++) {
            float4 wv = *(const float4*)&sW1[k * 128 + obase];
            double2 gd = *(const double2*)&shb[k * GSL + rg4];
            ull ga = dl(gd.x), gb = dl(gd.y);
            ull W0 = pk2(wv.x, wv.x), W1 = pk2(wv.y, wv.y);
            ull W2 = pk2(wv.z, wv.z), W3 = pk2(wv.w, wv.w);
            ffma2(acc[0][0], ga, W0); ffma2(acc[0][1], gb, W0);
            ffma2(acc[1][0], ga, W1); ffma2(acc[1][1], gb, W1);
            ffma2(acc[2][0], ga, W2); ffma2(acc[2][1], gb, W2);
            ffma2(acc[3][0], ga, W3); ffma2(acc[3][1], gb, W3);
        }

        if (w < 4) {
            #pragma unroll
            for (int j = 0; j < 4; j++) {
                int c = obase + j;                  // r col
                float2 p0 = upk2(acc[j][0]);
                float2 p1 = upk2(acc[j][1]);
                float s0 = fsig(p0.x), s1 = fsig(p0.y);
                float s2 = fsig(p1.x), s3 = fsig(p1.y);
                float4 h4 = *(const float4*)&shb[c * GSL + rg4];
                *(float4*)&sghr[c * GSL + rg4] =
                    make_float4(h4.x * s0, h4.y * s1, h4.z * s2, h4.w * s3);
            }
        } else {
            #pragma unroll
            for (int j = 0; j < 4; j++) {
                int c = obase - 64 + j;             // z col
                float2 p0 = upk2(acc[j][0]);
                float2 p1 = upk2(acc[j][1]);
                *(float4*)&szb[c * GSL + rg4] =
                    make_float4(fsig(p0.x), fsig(p0.y), fsig(p1.x), fsig(p1.y));
            }
        }
        __syncthreads();

        // ===== phase 2: hcand += (h*r) @ Wh2  (K = 64) =====
        ull a2[2][2];
        a2[0][0] = pk2(pv2[0].x, pv2[0].y); a2[0][1] = pk2(pv2[0].z, pv2[0].w);
        a2[1][0] = pk2(pv2[1].x, pv2[1].y); a2[1][1] = pk2(pv2[1].z, pv2[1].w);

        #pragma unroll 8
        for (int k = 0; k < 64; k++) {
            float2 wv = *(const float2*)&sWh2[k * 64 + c2base];
            double2 gd = *(const double2*)&sghr[k * GSL + rg4];
            ull ga = dl(gd.x), gb = dl(gd.y);
            ull W0 = pk2(wv.x, wv.x), W1 = pk2(wv.y, wv.y);
            ffma2(a2[0][0], ga, W0); ffma2(a2[0][1], gb, W0);
            ffma2(a2[1][0], ga, W1); ffma2(a2[1][1], gb, W1);
        }

        #pragma unroll
        for (int j = 0; j < 2; j++) {
            int c = c2base + j;
            float2 p0 = upk2(a2[j][0]);
            float2 p1 = upk2(a2[j][1]);
            float hc0 = ftanh_(p0.x), hc1 = ftanh_(p0.y);
            float hc2 = ftanh_(p1.x), hc3 = ftanh_(p1.y);
            float4 z4 = *(const float4*)&szb[c * GSL + rg4];
            float4 h4 = *(const float4*)&shb[c * GSL + rg4];
            *(float4*)&shb[c * GSL + rg4] =
                make_float4(fmaf(z4.x, hc0 - h4.x, h4.x),
                            fmaf(z4.y, hc1 - h4.y, h4.y),
                            fmaf(z4.z, hc2 - h4.z, h4.z),
                            fmaf(z4.w, hc3 - h4.w, h4.w));
        }
        pv1[0] = pn1[0]; pv1[1] = pn1[1]; pv1[2] = pn1[2]; pv1[3] = pn1[3];
        pv2[0] = pn2[0]; pv2[1] = pn2[1];
        __syncthreads();
    }

    #pragma unroll
    for (int j = 0; j < 2; j++) {
        int c = c2base + j;
        float4 h4 = *(const float4*)&shb[c * GSL + rg4];
        out[(size_t)(row0 + rg4 + 0) * DV + c] = h4.x;
        out[(size_t)(row0 + rg4 + 1) * DV + c] = h4.y;
        out[(size_t)(row0 + rg4 + 2) * DV + c] = h4.z;
        out[(size_t)(row0 + rg4 + 3) * DV + c] = h4.w;
    }
}

extern "C" void kernel_launch(void* const* d_in, const int* in_sizes, int n_in,
                              void* d_out, int out_size) {
    const float* x  = (const float*)d_in[0];
    const float* kh = (const float*)d_in[1];
    const float* kr = (const float*)d_in[2];
    const float* kz = (const float*)d_in[3];
    const float* bh = (const float*)d_in[4];
    const float* br = (const float*)d_in[5];
    const float* bz = (const float*)d_in[6];
    float* out = (float*)d_out;

    static bool attr_set = false;
    if (!attr_set) {
        cudaFuncSetAttribute(gru4d_pre_mma,
                             cudaFuncAttributeMaxDynamicSharedMemorySize,
                             PRE_SMEM_BYTES);
        cudaFuncSetAttribute(gru4d_seq_kernel,
                             cudaFuncAttributeMaxDynamicSharedMemorySize,
                             SQ_BYTES);
        attr_set = true;
    }
    gru4d_pre_mma<<<dim3(64, 128), 256, PRE_SMEM_BYTES>>>(x, kh, kr, kz, bh, br, bz);
    gru4d_seq_kernel<<<NCTA, NT, SQ_BYTES>>>(x, kh, kr, kz, out);
}

// round 17
// speedup vs baseline: 1.2425x; 1.1935x over previous
#include <cuda_runtime.h>
#include <cuda_bf16.h>
#include <cstdint>

// GRU over T2=256; 4096 independent rows.
// Kernel 1 (pre, mma.sync bf16 hi/lo): pre[t][o][row] = x_t @ Wx + bias,
//   3 cross products (hh, hl, lh), fp32 accum -> ~4e-6 accuracy.
//   R17: coalesced W staging, W converted once per CTA (8 t-blocks looped).
// Kernel 2 (seq, unchanged R13): 255-step recurrence, K=64 h-part only,
//   fp32 packed fma.rn.f32x2, acc initialized from prefetched pre[].

#define T2V 256
#define DV  64
#define NCTA 128
#define NT  256
#define GSL 32
#define NPRE_T 255
#define PRE_STEP 6144            // 192 cols * 32 rows per (row-block, t)

// 255 * 4096 * 192 floats = 802 MB scratch (sanctioned __device__ global)
__device__ float g_pre[(size_t)NPRE_T * 4096 * 192];

typedef unsigned long long ull;

// ---------------- packed f32x2 + activation helpers (seq kernel) -----------
__device__ __forceinline__ ull pk2(float lo, float hi) {
    ull r;
    asm("mov.b64 %0, {%1, %2};" : "=l"(r) : "f"(lo), "f"(hi));
    return r;
}
__device__ __forceinline__ float2 upk2(ull v) {
    float2 f;
    asm("mov.b64 {%0, %1}, %2;" : "=f"(f.x), "=f"(f.y) : "l"(v));
    return f;
}
__device__ __forceinline__ void ffma2(ull& d, ull a, ull b) {
    asm("fma.rn.f32x2 %0, %1, %2, %0;" : "+l"(d) : "l"(a), "l"(b));
}
__device__ __forceinline__ ull dl(double d) { return __double_as_longlong(d); }

__device__ __forceinline__ float fsig(float x) {
    float e;
    asm("ex2.approx.f32 %0, %1;" : "=f"(e) : "f"(x * -1.4426950408889634f));
    float r;
    asm("rcp.approx.f32 %0, %1;" : "=f"(r) : "f"(1.0f + e));
    return r;
}
__device__ __forceinline__ float ftanh_(float x) {
    return fmaf(2.0f, fsig(2.0f * x), -1.0f);
}

// ---------------- mma.sync helper (baseline PTX, no sm_103a features) ------
__device__ __forceinline__ void mma16816(float* c, uint32_t a0, uint32_t a1,
                                         uint32_t a2, uint32_t a3,
                                         uint32_t b0, uint32_t b1) {
    asm volatile("mma.sync.aligned.m16n8k16.row.col.f32.bf16.bf16.f32 "
                 "{%0,%1,%2,%3}, {%4,%5,%6,%7}, {%8,%9}, {%0,%1,%2,%3};"
                 : "+f"(c[0]), "+f"(c[1]), "+f"(c[2]), "+f"(c[3])
                 : "r"(a0), "r"(a1), "r"(a2), "r"(a3), "r"(b0), "r"(b1));
}

__device__ __forceinline__ uint32_t pbf2(float a, float b) {
    __nv_bfloat162 t = __floats2bfloat162_rn(a, b);
    uint32_t u;
    __builtin_memcpy(&u, &t, 4);
    return u;
}

// pre-kernel SMEM layout (uint32 units). Row stride 36 -> fragment LDS.32
// patterns map bank = (row*4 + j) % 32, conflict-free for both A and B frags.
#define SA_HI 0                        // A hi: 128 m-rows x 32 kpairs (+pad)
#define SA_LO (SA_HI + 128 * 36)
#define SB_HI (SA_LO + 128 * 36)       // B hi: 192 o-rows x 32 kpairs (+pad)
#define SB_LO (SB_HI + 192 * 36)
#define SBIAS (SB_LO + 192 * 36)       // 192 floats
#define PRE_U32 (SBIAS + 192)
#define PRE_SMEM_BYTES (PRE_U32 * 4)

// ===========================================================================
// Kernel 1: mma.sync precompute. grid = (8 t-superblocks, 128 row-blocks).
// Each CTA stages W fragments ONCE, then loops 8 t-blocks of 4 t each.
// M-tile = 4 t x 32 rows (m = tt*32 + r); o: gate g at [64g, 64g+64).
// ===========================================================================
__global__ void __launch_bounds__(256, 1)
gru4d_pre_mma(const float* __restrict__ x,
              const float* __restrict__ kh,
              const float* __restrict__ kr,
              const float* __restrict__ kz,
              const float* __restrict__ bh,
              const float* __restrict__ br,
              const float* __restrict__ bz) {
    extern __shared__ uint32_t su[];
    uint32_t* sAh = su + SA_HI;
    uint32_t* sAl = su + SA_LO;
    uint32_t* sBh = su + SB_HI;
    uint32_t* sBl = su + SB_LO;
    float*  sbias = (float*)(su + SBIAS);

    const int tid = threadIdx.x, w = tid >> 5, lane = tid & 31;
    const int l4 = lane >> 2, lm = lane & 3;
    const int rb = blockIdx.y;
    const int row0 = rb * 32;
    const size_t rstr = (size_t)T2V * DV;

    // ---- stage B ONCE: W[k][o] -> [o][kpair] bf16 hi/lo, coalesced over o ----
    for (int v = tid; v < 32 * 192; v += 256) {
        int jp  = v / 192;               // k-pair 0..31
        int col = v - jp * 192;          // o 0..191 (consecutive across lanes)
        int g = col >> 6, oc = col & 63;
        const float* W = (g == 0) ? kr : (g == 1) ? kz : kh;
        float w0 = W[(2 * jp) * 64 + oc];        // coalesced (oc contiguous)
        float w1 = W[(2 * jp + 1) * 64 + oc];    // coalesced
        float h0 = __bfloat162float(__float2bfloat16(w0));
        float h1 = __bfloat162float(__float2bfloat16(w1));
        sBh[col * 36 + jp] = pbf2(h0, h1);
        sBl[col * 36 + jp] = pbf2(w0 - h0, w1 - h1);
    }
    for (int o = tid; o < 192; o += 256)
        sbias[o] = (o < 64) ? br[o] : (o < 128) ? bz[o - 64] : bh[o - 128];

    // ---- loop over 8 t-blocks, reusing W fragments ----
    for (int it = 0; it < 8; ++it) {
        const int tb = blockIdx.x * 8 + it;
        const int t0 = 1 + 4 * tb;

        __syncthreads();   // prior iter's MMA reads of sA done (and W ready)

        // ---- stage A: x[t0..t0+3][row0..+31] -> bf16 hi/lo k-pairs ----
        #pragma unroll
        for (int i = 0; i < 8; i++) {
            int u  = tid + 256 * i;          // 0..2047
            int kq = u & 15;                 // float4 index within D=64
            int m  = u >> 4;                 // tt*32 + r
            int r  = m & 31, tt = m >> 5;
            int t  = t0 + tt; if (t > 255) t = 255;   // clamp (tail unused)
            float4 v = *(const float4*)&x[(size_t)(row0 + r) * rstr
                                          + (size_t)t * DV + 4 * kq];
            float hx = __bfloat162float(__float2bfloat16(v.x));
            float hy = __bfloat162float(__float2bfloat16(v.y));
            float hz = __bfloat162float(__float2bfloat16(v.z));
            float hw = __bfloat162float(__float2bfloat16(v.w));
            uint32_t* ph = &sAh[m * 36 + 2 * kq];
            uint32_t* pl = &sAl[m * 36 + 2 * kq];
            ph[0] = pbf2(hx, hy);             ph[1] = pbf2(hz, hw);
            pl[0] = pbf2(v.x - hx, v.y - hy); pl[1] = pbf2(v.z - hz, v.w - hw);
        }
        __syncthreads();

        // ---- MMAs: warp w owns m-rows [16w,16w+16); 24 n-tiles; 4 k-steps;
        //      3 combos (Ahi*Bhi, Ahi*Blo, Alo*Bhi), fp32 accum ----
        float acc[24][4];
        #pragma unroll
        for (int nt = 0; nt < 24; nt++)
            #pragma unroll
            for (int e = 0; e < 4; e++) acc[nt][e] = 0.0f;

        const int r0 = w * 16 + l4;
        #pragma unroll
        for (int comb = 0; comb < 3; comb++) {
            const uint32_t* A = (comb == 2) ? sAl : sAh;
            const uint32_t* B = (comb == 1) ? sBl : sBh;
            #pragma unroll
            for (int ks = 0; ks < 4; ks++) {
                int j0 = ks * 8 + lm;
                uint32_t a0 = A[r0 * 36 + j0];
                uint32_t a1 = A[(r0 + 8) * 36 + j0];
                uint32_t a2 = A[r0 * 36 + j0 + 4];
                uint32_t a3 = A[(r0 + 8) * 36 + j0 + 4];
                #pragma unroll
                for (int nt = 0; nt < 24; nt++) {
                    uint32_t b0 = B[(nt * 8 + l4) * 36 + j0];
                    uint32_t b1 = B[(nt * 8 + l4) * 36 + j0 + 4];
                    mma16816(acc[nt], a0, a1, a2, a3, b0, b1);
                }
            }
        }

        // ---- epilogue: add bias, store in [o][row32] layout ----
        {
            const int tt = w >> 1;                 // m = 16w + l4 -> tt
            const int t = t0 + tt;
            if (t <= 255) {
                const int rl = (w & 1) * 16 + l4;  // row within 32-row slab
                float* pp = g_pre + (size_t)rb * NPRE_T * PRE_STEP
                                  + (size_t)(t - 1) * PRE_STEP;
                #pragma unroll
                for (int nt = 0; nt < 24; nt++) {
                    int n0 = nt * 8 + lm * 2;
                    float b0v = sbias[n0], b1v = sbias[n0 + 1];
                    pp[n0 * 32 + rl]           = acc[nt][0] + b0v;
                    pp[(n0 + 1) * 32 + rl]     = acc[nt][1] + b1v;
                    pp[n0 * 32 + rl + 8]       = acc[nt][2] + b0v;
                    pp[(n0 + 1) * 32 + rl + 8] = acc[nt][3] + b1v;
                }
            }
        }
    }
}

// ===========================================================================
// Kernel 2: sequential recurrence, K=64 (h-part only). Unchanged from R13.
// ===========================================================================
#define SQ_W1  0                         // 64*128 : rows 64..127 of (Wr|Wz)
#define SQ_WH2 (64*128)                  // 64*64  : rows 64..127 of Wh
#define SQ_HB  (SQ_W1 + 64*128 + 64*64)  // 64*GSL : h[c][row]
#define SQ_GHR (SQ_HB + 64*GSL)          // 64*GSL : (h*r)[c][row]
#define SQ_ZB  (SQ_GHR + 64*GSL)         // 64*GSL : z[c][row]
#define SQ_FLOATS (SQ_ZB + 64*GSL)
#define SQ_BYTES (SQ_FLOATS * 4)

__global__ void __launch_bounds__(NT, 1)
gru4d_seq_kernel(const float* __restrict__ x,
                 const float* __restrict__ kh,
                 const float* __restrict__ kr,
                 const float* __restrict__ kz,
                 float* __restrict__ out) {
    extern __shared__ float sm[];
    float* sW1  = sm + SQ_W1;
    float* sWh2 = sm + SQ_WH2;
    float* shb  = sm + SQ_HB;
    float* sghr = sm + SQ_GHR;
    float* szb  = sm + SQ_ZB;

    const int tid  = threadIdx.x;
    const int w    = tid >> 5;
    const int lane = tid & 31;
    const int rg4  = (lane >> 2) * 4;
    const int cg   = lane & 3;
    const int obase  = 16 * w + 4 * cg;   // phase-1 cols (of 128)
    const int c2base = 8 * w + 2 * cg;    // phase-2 cols (of 64)
    const int row0 = blockIdx.x * 32;
    const size_t rstr = (size_t)T2V * DV;
    const size_t base = (size_t)blockIdx.x * NPRE_T * PRE_STEP;

    for (int idx = tid; idx < 64 * 128; idx += NT) {
        int k = idx >> 7, o = idx & 127;
        sW1[idx] = (o < 64) ? kr[(64 + k) * 64 + o] : kz[(64 + k) * 64 + (o - 64)];
    }
    for (int idx = tid; idx < 64 * 64; idx += NT) {
        int k = idx >> 6, o = idx & 63;
        sWh2[idx] = kh[(64 + k) * 64 + o];
    }

    #pragma unroll
    for (int j = 0; j < 2; j++) {
        int c = c2base + j;
        #pragma unroll
        for (int i = 0; i < 4; i++)
            shb[c * GSL + rg4 + i] = x[(size_t)(row0 + rg4 + i) * rstr + c];
    }
    __syncthreads();

    float4 pv1[4], pv2[2];
    {
        const float* pp = g_pre + base;   // t=1
        #pragma unroll
        for (int j = 0; j < 4; j++)
            pv1[j] = *(const float4*)&pp[(obase + j) * 32 + rg4];
        #pragma unroll
        for (int j = 0; j < 2; j++)
            pv2[j] = *(const float4*)&pp[(128 + c2base + j) * 32 + rg4];
    }

    for (int t = 1; t < T2V; ++t) {
        float4 pn1[4], pn2[2];
        if (t < T2V - 1) {
            const float* pp = g_pre + base + (size_t)t * PRE_STEP;  // t+1
            #pragma unroll
            for (int j = 0; j < 4; j++)
                pn1[j] = *(const float4*)&pp[(obase + j) * 32 + rg4];
            #pragma unroll
            for (int j = 0; j < 2; j++)
                pn2[j] = *(const float4*)&pp[(128 + c2base + j) * 32 + rg4];
        }

        // ===== phase 1: r|z += h @ W1  (K = 64) =====
        ull acc[4][2];
        #pragma unroll
        for (int j = 0; j < 4; j++) {
            acc[j][0] = pk2(pv1[j].x, pv1[j].y);
            acc[j][1] = pk2(pv1[j].z, pv1[j].w);
        }
        #pragma unroll 8
        for (int k = 0; k < 64; k++) {
            float4 wv = *(const float4*)&sW1[k * 128 + obase];
            double2 gd = *(const double2*)&shb[k * GSL + rg4];
            ull ga = dl(gd.x), gb = dl(gd.y);
            ull W0 = pk2(wv.x, wv.x), W1 = pk2(wv.y, wv.y);
            ull W2 = pk2(wv.z, wv.z), W3 = pk2(wv.w, wv.w);
            ffma2(acc[0][0], ga, W0); ffma2(acc[0][1], gb, W0);
            ffma2(acc[1][0], ga, W1); ffma2(acc[1][1], gb, W1);
            ffma2(acc[2][0], ga, W2); ffma2(acc[2][1], gb, W2);
            ffma2(acc[3][0], ga, W3); ffma2(acc[3][1], gb, W3);
        }

        if (w < 4) {
            #pragma unroll
            for (int j = 0; j < 4; j++) {
                int c = obase + j;                  // r col
                float2 p0 = upk2(acc[j][0]);
                float2 p1 = upk2(acc[j][1]);
                float s0 = fsig(p0.x), s1 = fsig(p0.y);
                float s2 = fsig(p1.x), s3 = fsig(p1.y);
                float4 h4 = *(const float4*)&shb[c * GSL + rg4];
                *(float4*)&sghr[c * GSL + rg4] =
                    make_float4(h4.x * s0, h4.y * s1, h4.z * s2, h4.w * s3);
            }
        } else {
            #pragma unroll
            for (int j = 0; j < 4; j++) {
                int c = obase - 64 + j;             // z col
                float2 p0 = upk2(acc[j][0]);
                float2 p1 = upk2(acc[j][1]);
                *(float4*)&szb[c * GSL + rg4] =
                    make_float4(fsig(p0.x), fsig(p0.y), fsig(p1.x), fsig(p1.y));
            }
        }
        __syncthreads();

        // ===== phase 2: hcand += (h*r) @ Wh2  (K = 64) =====
        ull a2[2][2];
        a2[0][0] = pk2(pv2[0].x, pv2[0].y); a2[0][1] = pk2(pv2[0].z, pv2[0].w);
        a2[1][0] = pk2(pv2[1].x, pv2[1].y); a2[1][1] = pk2(pv2[1].z, pv2[1].w);

        #pragma unroll 8
        for (int k = 0; k < 64; k++) {
            float2 wv = *(const float2*)&sWh2[k * 64 + c2base];
            double2 gd = *(const double2*)&sghr[k * GSL + rg4];
            ull ga = dl(gd.x), gb = dl(gd.y);
            ull W0 = pk2(wv.x, wv.x), W1 = pk2(wv.y, wv.y);
            ffma2(a2[0][0], ga, W0); ffma2(a2[0][1], gb, W0);
            ffma2(a2[1][0], ga, W1); ffma2(a2[1][1], gb, W1);
        }

        #pragma unroll
        for (int j = 0; j < 2; j++) {
            int c = c2base + j;
            float2 p0 = upk2(a2[j][0]);
            float2 p1 = upk2(a2[j][1]);
            float hc0 = ftanh_(p0.x), hc1 = ftanh_(p0.y);
            float hc2 = ftanh_(p1.x), hc3 = ftanh_(p1.y);
            float4 z4 = *(const float4*)&szb[c * GSL + rg4];
            float4 h4 = *(const float4*)&shb[c * GSL + rg4];
            *(float4*)&shb[c * GSL + rg4] =
                make_float4(fmaf(z4.x, hc0 - h4.x, h4.x),
                            fmaf(z4.y, hc1 - h4.y, h4.y),
                            fmaf(z4.z, hc2 - h4.z, h4.z),
                            fmaf(z4.w, hc3 - h4.w, h4.w));
        }
        pv1[0] = pn1[0]; pv1[1] = pn1[1]; pv1[2] = pn1[2]; pv1[3] = pn1[3];
        pv2[0] = pn2[0]; pv2[1] = pn2[1];
        __syncthreads();
    }

    #pragma unroll
    for (int j = 0; j < 2; j++) {
        int c = c2base + j;
        float4 h4 = *(const float4*)&shb[c * GSL + rg4];
        out[(size_t)(row0 + rg4 + 0) * DV + c] = h4.x;
        out[(size_t)(row0 + rg4 + 1) * DV + c] = h4.y;
        out[(size_t)(row0 + rg4 + 2) * DV + c] = h4.z;
        out[(size_t)(row0 + rg4 + 3) * DV + c] = h4.w;
    }
}

extern "C" void kernel_launch(void* const* d_in, const int* in_sizes, int n_in,
                              void* d_out, int out_size) {
    const float* x  = (const float*)d_in[0];
    const float* kh = (const float*)d_in[1];
    const float* kr = (const float*)d_in[2];
    const float* kz = (const float*)d_in[3];
    const float* bh = (const float*)d_in[4];
    const float* br = (const float*)d_in[5];
    const float* bz = (const float*)d_in[6];
    float* out = (float*)d_out;

    static bool attr_set = false;
    if (!attr_set) {
        cudaFuncSetAttribute(gru4d_pre_mma,
                             cudaFuncAttributeMaxDynamicSharedMemorySize,
                             PRE_SMEM_BYTES);
        cudaFuncSetAttribute(gru4d_seq_kernel,
                             cudaFuncAttributeMaxDynamicSharedMemorySize,
                             SQ_BYTES);
        attr_set = true;
    }
    gru4d_pre_mma<<<dim3(8, 128), 256, PRE_SMEM_BYTES>>>(x, kh, kr, kz, bh, br, bz);
    gru4d_seq_kernel<<<NCTA, NT, SQ_BYTES>>>(x, kh, kr, kz, out);
}